// round 13
// baseline (speedup 1.0000x reference)
#include <cuda_runtime.h>
#include <cstddef>

// Raster_87205015978273: per-depo 10x10x10 Gaussian raster patches.
// Output buffer (all float32): [N*1000] rasters, then [N*3] offsets (exact
// integer values stored as float).
//
// R11: persistent warp-per-depo. Grid = 888 blocks (148 SM x 6), each warp
// grid-strides over depos. Next depo's input LDGs are issued at the top of
// each iteration (register rotation) so their ~600-cycle latency hides under
// the current depo's erff + yz + store stream. All sync is __syncwarp.

#define WARPS    8
#define NTHREADS 256
#define GRIDB    888      // 148 SMs * 6 resident blocks

__global__ __launch_bounds__(NTHREADS, 6)
void raster_kernel(const float* __restrict__ sigma,   // [N,3]
                   const float* __restrict__ time,    // [N]
                   const float* __restrict__ charge,  // [N]
                   const float* __restrict__ tail,    // [N,3]
                   const float* __restrict__ gs,      // [3]
                   const float* __restrict__ nsig,    // [1]
                   float* __restrict__ out_r,         // [N,10,10,10] f32
                   float* __restrict__ out_o,         // [N,3] offsets as f32
                   int N)
{
    __shared__ float  sw[WARPS][32];    // [w][d*10+j]: d=0 -> charge*wx, d=1 wy, d=2 wz
    __shared__ float4 yz4[WARPS][25];   // [w][jk/4]: wy[j]*wz[k]

    const int t    = threadIdx.x;
    const int wid  = t >> 5;
    const int lane = t & 31;
    const int stride = gridDim.x * WARPS;

    const bool act = (lane < 30);
    const int  d   = act ? (lane / 10) : 0;      // dim 0,1,2
    const int  j   = act ? (lane - d * 10) : 0;  // cell 0..9
    const float h  = act ? gs[d] : 1.0f;
    const float ns = nsig[0];

    int n = blockIdx.x * WARPS + wid;

    // prime the pipeline: load inputs for the first depo
    float cur_c = 0.f, cur_s = 1.f, cur_q = 0.f;
    if (act && n < N) {
        cur_c = (d == 0) ? tail[3 * n + 1]
              : (d == 1) ? tail[3 * n + 2]
                         : time[n];
        cur_s = sigma[3 * n + d];
        cur_q = charge[n];
    }

    while (n < N) {
        const int nn = n + stride;

        // ---- prefetch next depo's inputs (LDGs issue now, consumed next iter) ----
        float nxt_c = 0.f, nxt_s = 1.f, nxt_q = 0.f;
        if (act && nn < N) {
            nxt_c = (d == 0) ? tail[3 * nn + 1]
                  : (d == 1) ? tail[3 * nn + 2]
                             : time[nn];
            nxt_s = sigma[3 * nn + d];
            nxt_q = charge[nn];
        }

        // ---- Phase A: per-dim cell integrals + offsets (current depo) ----
        if (act) {
            const float imin = floorf((cur_c - ns * cur_s) / h);
            const float inv  = 1.0f / (1.41421356237309515f * cur_s);
            const float e0 = (imin + (float)j) * h;
            const float e1 = (imin + (float)(j + 1)) * h;
            float w = 0.5f * (erff((e1 - cur_c) * inv) - erff((e0 - cur_c) * inv));
            if (d == 0) w *= cur_q;                  // fold charge into x weights
            sw[wid][d * 10 + j] = w;
            if (j == 0) out_o[3 * n + d] = imin;     // offsets as float values
        }
        __syncwarp();

        // ---- Phase B: yz[jk] = wy[j]*wz[k] (100 values per warp) ----
        {
            float* yzf = (float*)&yz4[wid][0];   // 100 floats
            #pragma unroll
            for (int l = 0; l < 4; l++) {
                const int p = lane + (l << 5);   // 0..127
                if (l < 3 || p < 100) {
                    const int jj = p / 10;
                    const int kk = p - jj * 10;
                    yzf[p] = sw[wid][10 + jj] * sw[wid][20 + kk];
                }
            }
        }
        __syncwarp();

        // ---- Phase C: 250 float4 streaming stores, two depth-4 batches ----
        float* dst = out_r + (size_t)n * 1000;

        #pragma unroll
        for (int half = 0; half < 2; half++) {
            float4 z[4];
            float  s[4];
            int    q4[4];

            #pragma unroll
            for (int l = 0; l < 4; l++) {
                int q = lane + ((half * 4 + l) << 5);   // 0..255
                q4[l] = q;
                int qc = (q > 249) ? 249 : q;           // clamp tail
                int i   = qc / 25;                      // x-slab (0..9)
                int jk4 = qc - i * 25;                  // float4 in yz plane
                z[l] = yz4[wid][jk4];
                s[l] = sw[wid][i];                      // charge*wx[i]
            }

            #pragma unroll
            for (int l = 0; l < 4; l++) {
                z[l].x *= s[l];
                z[l].y *= s[l];
                z[l].z *= s[l];
                z[l].w *= s[l];
            }

            #pragma unroll
            for (int l = 0; l < 4; l++) {
                if (half == 0 || l < 3 || q4[l] < 250) {
                    __stcs(reinterpret_cast<float4*>(dst + q4[l] * 4), z[l]);
                }
            }
        }
        __syncwarp();   // protect sw/yz4 from next iteration's Phase A writes

        // rotate pipeline registers
        cur_c = nxt_c;
        cur_s = nxt_s;
        cur_q = nxt_q;
        n = nn;
    }
}

extern "C" void kernel_launch(void* const* d_in, const int* in_sizes, int n_in,
                              void* d_out, int out_size)
{
    const float* sigma  = (const float*)d_in[0];
    const float* time   = (const float*)d_in[1];
    const float* charge = (const float*)d_in[2];
    const float* tail   = (const float*)d_in[3];
    const float* gs     = (const float*)d_in[4];
    const float* nsig   = (const float*)d_in[5];

    const int N = in_sizes[1];             // time has N elements
    float* out_r = (float*)d_out;
    float* out_o = out_r + (size_t)N * 1000;

    raster_kernel<<<GRIDB, NTHREADS>>>(sigma, time, charge, tail, gs, nsig,
                                       out_r, out_o, N);
}

// round 14
// speedup vs baseline: 1.1794x; 1.1794x over previous
#include <cuda_runtime.h>
#include <cstddef>

// Raster_87205015978273: per-depo 10x10x10 Gaussian raster patches.
// Output buffer (all float32): [N*1000] rasters, then [N*3] offsets (exact
// integer values stored as float).
//
// R14: R8 structure (warp-per-depo, DPB=8, depth-4 store batches, __stcs)
// with the per-store LDS.32 of s=charge*wx[i] replaced by a register shuffle
// from lane i (which computed it in phase A). LSU ops per float4: 3 -> 2.

#define DPB 8        // depos per block: one warp each
#define NTHREADS 256

__global__ __launch_bounds__(NTHREADS, 8)
void raster_kernel(const float* __restrict__ sigma,   // [N,3]
                   const float* __restrict__ time,    // [N]
                   const float* __restrict__ charge,  // [N]
                   const float* __restrict__ tail,    // [N,3]
                   const float* __restrict__ gs,      // [3]
                   const float* __restrict__ nsig,    // [1]
                   float* __restrict__ out_r,         // [N,10,10,10] f32
                   float* __restrict__ out_o,         // [N,3] offsets as f32
                   int N)
{
    __shared__ float  sw[DPB][32];      // [w][d*10+j]: only d=1 (wy), d=2 (wz) used
    __shared__ float4 yz4[DPB][25];     // [w][jk/4]: wy[j]*wz[k], jk = j*10+k

    const int t    = threadIdx.x;
    const int wid  = t >> 5;            // warp = depo slot
    const int lane = t & 31;
    const int n    = blockIdx.x * DPB + wid;

    float wreg = 0.0f;                  // lane i (0..9) holds charge*wx[i]

    if (n < N) {
        // ---- Phase A: per-dim cell integrals (30 lanes) + offsets ----
        if (lane < 30) {
            const int d = lane / 10;     // dim 0,1,2
            const int j = lane - d * 10; // cell 0..9
            // center = [tail[:,1], tail[:,2], time]
            float c = (d == 0) ? tail[3 * n + 1]
                    : (d == 1) ? tail[3 * n + 2]
                               : time[n];
            const float s  = sigma[3 * n + d];
            const float h  = gs[d];
            const float ns = nsig[0];

            const float imin = floorf((c - ns * s) / h);
            const float inv  = 1.0f / (1.41421356237309515f * s);
            const float e0 = (imin + (float)j) * h;
            const float e1 = (imin + (float)(j + 1)) * h;
            float w = 0.5f * (erff((e1 - c) * inv) - erff((e0 - c) * inv));
            if (d == 0) {
                w *= charge[n];                      // fold charge into x weights
                wreg = w;                            // stays in lane j's register
            } else {
                sw[wid][d * 10 + j] = w;             // wy, wz go to shared
            }
            if (j == 0) out_o[3 * n + d] = imin;     // offsets as float values
        }
        __syncwarp();

        // ---- Phase B: yz[jk] = wy[j]*wz[k] (100 values per warp) ----
        {
            float* yzf = (float*)&yz4[wid][0];   // 100 floats
            #pragma unroll
            for (int l = 0; l < 4; l++) {
                const int p = lane + (l << 5);   // 0..127
                if (l < 3 || p < 100) {
                    const int jj = p / 10;
                    const int kk = p - jj * 10;
                    yzf[p] = sw[wid][10 + jj] * sw[wid][20 + kk];
                }
            }
        }
        __syncwarp();

        // ---- Phase C: 250 float4 streaming stores per warp, 2 batches of 4.
        //      s fetched by shuffle from lane i's wreg (no LDS.32). ----
        float* dst = out_r + (size_t)n * 1000;

        #pragma unroll
        for (int half = 0; half < 2; half++) {
            float4 z[4];
            float  s[4];
            int    q4[4];

            #pragma unroll
            for (int l = 0; l < 4; l++) {
                int q = lane + ((half * 4 + l) << 5);   // 0..255
                q4[l] = q;
                int qc = (q > 249) ? 249 : q;           // clamp tail
                int i   = qc / 25;                      // x-slab (0..9)
                int jk4 = qc - i * 25;                  // float4 index in yz plane
                z[l] = yz4[wid][jk4];
                s[l] = __shfl_sync(0xFFFFFFFFu, wreg, i);  // charge*wx[i]
            }

            #pragma unroll
            for (int l = 0; l < 4; l++) {
                z[l].x *= s[l];
                z[l].y *= s[l];
                z[l].z *= s[l];
                z[l].w *= s[l];
            }

            #pragma unroll
            for (int l = 0; l < 4; l++) {
                if (half == 0 || l < 3 || q4[l] < 250) {
                    __stcs(reinterpret_cast<float4*>(dst + q4[l] * 4), z[l]);
                }
            }
        }
    }
}

extern "C" void kernel_launch(void* const* d_in, const int* in_sizes, int n_in,
                              void* d_out, int out_size)
{
    const float* sigma  = (const float*)d_in[0];
    const float* time   = (const float*)d_in[1];
    const float* charge = (const float*)d_in[2];
    const float* tail   = (const float*)d_in[3];
    const float* gs     = (const float*)d_in[4];
    const float* nsig   = (const float*)d_in[5];

    const int N = in_sizes[1];             // time has N elements
    float* out_r = (float*)d_out;
    float* out_o = out_r + (size_t)N * 1000;

    const int grid = (N + DPB - 1) / DPB;
    raster_kernel<<<grid, NTHREADS>>>(sigma, time, charge, tail, gs, nsig,
                                      out_r, out_o, N);
}

// round 15
// speedup vs baseline: 1.1801x; 1.0005x over previous
#include <cuda_runtime.h>
#include <cstddef>

// Raster_87205015978273: per-depo 10x10x10 Gaussian raster patches.
// Output buffer (all float32): [N*1000] rasters, then [N*3] offsets (exact
// integer values stored as float).
//
// R14: R8 structure (warp-per-depo, DPB=8, depth-4 store batches, __stcs)
// with the per-store LDS.32 of s=charge*wx[i] replaced by a register shuffle
// from lane i (which computed it in phase A). LSU ops per float4: 3 -> 2.

#define DPB 8        // depos per block: one warp each
#define NTHREADS 256

__global__ __launch_bounds__(NTHREADS, 8)
void raster_kernel(const float* __restrict__ sigma,   // [N,3]
                   const float* __restrict__ time,    // [N]
                   const float* __restrict__ charge,  // [N]
                   const float* __restrict__ tail,    // [N,3]
                   const float* __restrict__ gs,      // [3]
                   const float* __restrict__ nsig,    // [1]
                   float* __restrict__ out_r,         // [N,10,10,10] f32
                   float* __restrict__ out_o,         // [N,3] offsets as f32
                   int N)
{
    __shared__ float  sw[DPB][32];      // [w][d*10+j]: only d=1 (wy), d=2 (wz) used
    __shared__ float4 yz4[DPB][25];     // [w][jk/4]: wy[j]*wz[k], jk = j*10+k

    const int t    = threadIdx.x;
    const int wid  = t >> 5;            // warp = depo slot
    const int lane = t & 31;
    const int n    = blockIdx.x * DPB + wid;

    float wreg = 0.0f;                  // lane i (0..9) holds charge*wx[i]

    if (n < N) {
        // ---- Phase A: per-dim cell integrals (30 lanes) + offsets ----
        if (lane < 30) {
            const int d = lane / 10;     // dim 0,1,2
            const int j = lane - d * 10; // cell 0..9
            // center = [tail[:,1], tail[:,2], time]
            float c = (d == 0) ? tail[3 * n + 1]
                    : (d == 1) ? tail[3 * n + 2]
                               : time[n];
            const float s  = sigma[3 * n + d];
            const float h  = gs[d];
            const float ns = nsig[0];

            const float imin = floorf((c - ns * s) / h);
            const float inv  = 1.0f / (1.41421356237309515f * s);
            const float e0 = (imin + (float)j) * h;
            const float e1 = (imin + (float)(j + 1)) * h;
            float w = 0.5f * (erff((e1 - c) * inv) - erff((e0 - c) * inv));
            if (d == 0) {
                w *= charge[n];                      // fold charge into x weights
                wreg = w;                            // stays in lane j's register
            } else {
                sw[wid][d * 10 + j] = w;             // wy, wz go to shared
            }
            if (j == 0) out_o[3 * n + d] = imin;     // offsets as float values
        }
        __syncwarp();

        // ---- Phase B: yz[jk] = wy[j]*wz[k] (100 values per warp) ----
        {
            float* yzf = (float*)&yz4[wid][0];   // 100 floats
            #pragma unroll
            for (int l = 0; l < 4; l++) {
                const int p = lane + (l << 5);   // 0..127
                if (l < 3 || p < 100) {
                    const int jj = p / 10;
                    const int kk = p - jj * 10;
                    yzf[p] = sw[wid][10 + jj] * sw[wid][20 + kk];
                }
            }
        }
        __syncwarp();

        // ---- Phase C: 250 float4 streaming stores per warp, 2 batches of 4.
        //      s fetched by shuffle from lane i's wreg (no LDS.32). ----
        float* dst = out_r + (size_t)n * 1000;

        #pragma unroll
        for (int half = 0; half < 2; half++) {
            float4 z[4];
            float  s[4];
            int    q4[4];

            #pragma unroll
            for (int l = 0; l < 4; l++) {
                int q = lane + ((half * 4 + l) << 5);   // 0..255
                q4[l] = q;
                int qc = (q > 249) ? 249 : q;           // clamp tail
                int i   = qc / 25;                      // x-slab (0..9)
                int jk4 = qc - i * 25;                  // float4 index in yz plane
                z[l] = yz4[wid][jk4];
                s[l] = __shfl_sync(0xFFFFFFFFu, wreg, i);  // charge*wx[i]
            }

            #pragma unroll
            for (int l = 0; l < 4; l++) {
                z[l].x *= s[l];
                z[l].y *= s[l];
                z[l].z *= s[l];
                z[l].w *= s[l];
            }

            #pragma unroll
            for (int l = 0; l < 4; l++) {
                if (half == 0 || l < 3 || q4[l] < 250) {
                    __stcs(reinterpret_cast<float4*>(dst + q4[l] * 4), z[l]);
                }
            }
        }
    }
}

extern "C" void kernel_launch(void* const* d_in, const int* in_sizes, int n_in,
                              void* d_out, int out_size)
{
    const float* sigma  = (const float*)d_in[0];
    const float* time   = (const float*)d_in[1];
    const float* charge = (const float*)d_in[2];
    const float* tail   = (const float*)d_in[3];
    const float* gs     = (const float*)d_in[4];
    const float* nsig   = (const float*)d_in[5];

    const int N = in_sizes[1];             // time has N elements
    float* out_r = (float*)d_out;
    float* out_o = out_r + (size_t)N * 1000;

    const int grid = (N + DPB - 1) / DPB;
    raster_kernel<<<grid, NTHREADS>>>(sigma, time, charge, tail, gs, nsig,
                                      out_r, out_o, N);
}